// round 17
// baseline (speedup 1.0000x reference)
#include <cuda_runtime.h>
#include <cuda_fp16.h>

#define NBANDS 100
#define TT 19
#define FFb 513
#define BB 256
#define KTOT 528          // 400 feat + 128 h (= 33 k-tiles of 16)
#define GC 512            // gate columns: rz(256) | i_n(128) | h_n(128)
#define WINLEN 842
#define FSAMP 16000
#define NTHR 512          // 16 warps; one batch row per block
#define NKT 33            // k-tiles (GRU)
#define WB_UINTS (32*NKT*32*4)   // GRU B-fragment weights, 135168 uints
#define M1_U2 (16*8*32)          // MLP1 frag uint2 count (4096)
#define M2_U2 (16*8*32)
#define M3_U2 (13*8*32)          // head (104 cols, 100 used)

// ---------------- device state / scratch ----------------
__device__ float d_fc[NBANDS], d_q0[NBANDS], d_dq[NBANDS];
__device__ __align__(16) unsigned d_Wb[WB_UINTS];  // GRU mma B-frags
__device__ __align__(16) uint2 d_Wm1[M1_U2];       // MLP1 B-frags (fp16)
__device__ __align__(16) uint2 d_Wm2[M2_U2];
__device__ __align__(16) uint2 d_Wm3[M3_U2];
__device__ float d_biasc[GC];
__device__ __align__(16) float2 d_mag[BB*TT*FFb];  // (|L|,|R|)

// ---------------- constants (ERB scale) ----------------
__global__ void k_consts() {
    int n = threadIdx.x;
    if (n < NBANDS) {
        double E0 = 21.4 * log10(4.37 * 50.0   / 1000.0 + 1.0);
        double E1 = 21.4 * log10(4.37 * 7200.0 / 1000.0 + 1.0);
        double E  = E0 + (E1 - E0) * ((double)n / 99.0);
        double fc = (pow(10.0, E / 21.4) - 1.0) * 1000.0 / 4.37;
        double erb = 24.7 * (4.37 * fc / 1000.0 + 1.0);
        double q0 = fc / (1.019 * erb);
        double En = (E - E0) / (E1 - E0 + 1e-12);
        double dq = 2.0 * (0.5 + 0.5 * En);
        if (dq < 0.001) dq = 0.001;
        d_fc[n] = (float)fc; d_q0[n] = (float)q0; d_dq[n] = (float)dq;
    }
}

__device__ __forceinline__ float wcomb(const float* w_ih, const float* w_hh, int col, int k) {
    if (k >= KTOT) return 0.f;
    if (col < 256) return (k < 400) ? w_ih[col*400 + k] : w_hh[col*128 + (k-400)];
    if (col < 384) return (k < 400) ? w_ih[col*400 + k] : 0.f;
    return (k < 400) ? 0.f : w_hh[(col-128)*128 + (k-400)];
}

// Pack one MLP fragment element: e -> (w,kt,lane); W is [Nout][128] row-major.
__device__ __forceinline__ uint2 pack_mlp(const float* W, int Nout, int e) {
    int lane = e & 31, kt = (e >> 5) & 7, w = e >> 8;
    int n  = w*8 + (lane >> 2);
    int kb = kt*16 + (lane & 3)*2;
    float a0 = 0.f, a1 = 0.f, a2 = 0.f, a3 = 0.f;
    if (n < Nout) {
        a0 = W[n*128 + kb];     a1 = W[n*128 + kb + 1];
        a2 = W[n*128 + kb + 8]; a3 = W[n*128 + kb + 9];
    }
    __half2 h0 = __floats2half2_rn(a0, a1);
    __half2 h1 = __floats2half2_rn(a2, a3);
    uint2 r; r.x = *(unsigned*)&h0; r.y = *(unsigned*)&h1;
    return r;
}

// Build all fragment-packed weights + GRU bias
__global__ void k_prep(const float* __restrict__ w_ih, const float* __restrict__ w_hh,
                       const float* __restrict__ b_ih, const float* __restrict__ b_hh,
                       const float* __restrict__ w1, const float* __restrict__ w2,
                       const float* __restrict__ w3) {
    int i = blockIdx.x * blockDim.x + threadIdx.x;
    if (i < WB_UINTS) {
        int tmp = i;
        int j    = tmp & 3;  tmp >>= 2;
        int lane = tmp & 31; tmp >>= 5;
        int kt   = tmp % NKT;
        int warp = tmp / NKT;
        int ntile = j >> 1, reg = j & 1;
        int n  = warp*16 + ntile*8 + (lane >> 2);
        int kb = kt*16 + (lane & 3)*2 + reg*8;
        float v0 = wcomb(w_ih, w_hh, n, kb);
        float v1 = wcomb(w_ih, w_hh, n, kb + 1);
        __half2 h = __floats2half2_rn(v0, v1);
        d_Wb[i] = *(unsigned*)&h;
        return;
    }
    int j = i - WB_UINTS;
    if (j < GC) {
        float v;
        if (j < 256)      v = b_ih[j] + b_hh[j];
        else if (j < 384) v = b_ih[j];
        else              v = b_hh[j - 128];
        d_biasc[j] = v;
        return;
    }
    j -= GC;
    if (j < M1_U2) { d_Wm1[j] = pack_mlp(w1, 128, j); return; }
    j -= M1_U2;
    if (j < M2_U2) { d_Wm2[j] = pack_mlp(w2, 128, j); return; }
    j -= M2_U2;
    if (j < M3_U2) { d_Wm3[j] = pack_mlp(w3, 100, j); }
}

// ---------------- packed L+iR 1024-pt FFT per (b,t), smem twiddles ----------------
__global__ void k_fft(const float* __restrict__ wavL, const float* __restrict__ wavR,
                      float* __restrict__ outXL, float* __restrict__ outXR,
                      int realmode, long long xl_off, long long xr_off, long long out_elems) {
    __shared__ float2 z[1024];
    __shared__ float2 twt[1023];
    int bt = blockIdx.x;
    int b = bt / TT, t = bt - b * TT;
    int tid = threadIdx.x;
    const float* wl = wavL + b * FSAMP + t * WINLEN;
    const float* wr = wavR + b * FSAMP + t * WINLEN;

    for (int g = tid; g < 1023; g += 256) {
        int hb = 31 - __clz(g + 1);
        int half = 1 << hb;
        int j = g + 1 - half;
        float s, c;
        __sincosf(-3.14159265358979f * (float)j / (float)half, &s, &c);
        twt[g] = make_float2(c, s);
    }
    for (int j = tid; j < 1024; j += 256) {
        float2 v = make_float2(0.f, 0.f);
        if (j < WINLEN) {
            float w = 0.5f - 0.5f * cosf(6.2831853071795864f * (float)j / (float)WINLEN);
            v.x = wl[j] * w; v.y = wr[j] * w;
        }
        z[__brev((unsigned)j) >> 22] = v;
    }
    __syncthreads();

    for (int len = 2; len <= 1024; len <<= 1) {
        int half = len >> 1;
        for (int i = tid; i < 512; i += 256) {
            int j = i & (half - 1);
            int base = ((i - j) << 1) + j;
            float2 w2 = twt[half - 1 + j];
            float c = w2.x, s = w2.y;
            float2 u = z[base], v = z[base + half];
            float tr = v.x * c - v.y * s;
            float ti = v.x * s + v.y * c;
            z[base]        = make_float2(u.x + tr, u.y + ti);
            z[base + half] = make_float2(u.x - tr, u.y - ti);
        }
        __syncthreads();
    }

    for (int k = tid; k < FFb; k += 256) {
        float2 zk = z[k];
        float2 zm = z[(1024 - k) & 1023];
        float lr = 0.5f * (zk.x + zm.x), li = 0.5f * (zk.y - zm.y);
        float rr = 0.5f * (zk.y + zm.y), ri = 0.5f * (zm.x - zk.x);
        long long o = (long long)bt * FFb + k;
        if (realmode) {
            outXL[o] = lr;
            outXR[o] = rr;
        } else {
            long long base2 = o * 2;
            if (xl_off + base2 + 1 < out_elems) {
                outXL[base2] = lr; outXL[base2 + 1] = li;
            }
            if (xr_off + base2 + 1 < out_elems) {
                outXR[base2] = rr; outXR[base2 + 1] = ri;
            }
        }
        d_mag[o] = make_float2(sqrtf(lr * lr + li * li), sqrtf(rr * rr + ri * ri));
    }
}

__device__ __forceinline__ void mma16816(float& d0, float& d1, float& d2, float& d3,
                                         unsigned a0, unsigned a1, unsigned a2, unsigned a3,
                                         unsigned b0, unsigned b1) {
    asm volatile(
        "mma.sync.aligned.m16n8k16.row.col.f32.f16.f16.f32 "
        "{%0,%1,%2,%3}, {%4,%5,%6,%7}, {%8,%9}, {%0,%1,%2,%3};"
        : "+f"(d0), "+f"(d1), "+f"(d2), "+f"(d3)
        : "r"(a0), "r"(a1), "r"(a2), "r"(a3), "r"(b0), "r"(b1));
}

// 8-ktile (K=128) mma chain; single-row A (row 0), fp16 contiguous.
// Valid outputs on lanes 0..3: cols 2*(lane&3), +1 within the warp's 8-col group.
__device__ __forceinline__ float2 mlp_mma8(const uint2* __restrict__ wf,
                                           const __half* __restrict__ A, int lane) {
    float d0 = 0.f, d1 = 0.f, d2 = 0.f, d3 = 0.f;
    int q = lane & 3;
    bool alive = (lane < 4);
#pragma unroll
    for (int kt = 0; kt < 8; kt++) {
        uint2 b = wf[kt*32 + lane];
        unsigned x0 = 0, x2 = 0;
        if (alive) {
            int kk = kt*16 + 2*q;
            x0 = *(const unsigned*)&A[kk];
            x2 = *(const unsigned*)&A[kk + 8];
        }
        mma16816(d0, d1, d2, d3, x0, 0u, x2, 0u, b.x, b.y);
    }
    return make_float2(d0, d1);
}

// ---------------- persistent scan: all 19 steps, 1 batch row per block ----------------
__global__ void __launch_bounds__(NTHR) k_steps(
        float* __restrict__ outYL, float* __restrict__ outYR, float* __restrict__ outQ,
        const float* __restrict__ b1, const float* __restrict__ g1, const float* __restrict__ be1,
        const float* __restrict__ b2, const float* __restrict__ g2, const float* __restrict__ be2,
        const float* __restrict__ b3) {
    __shared__ __align__(16) __half ahr[KTOT];     // fp16 activations (feat|h), row 0
    __shared__ __align__(16) __half am1[128];      // MLP layer outputs fp16
    __shared__ __align__(16) __half am2[128];
    __shared__ __align__(16) float gs[GC];         // fp32 gate sums (GRU mma)
    __shared__ float2 magbuf[2][FFb];              // double-buffered magnitudes
    __shared__ float hold_s[128];
    __shared__ float Qs[NBANDS];
    __shared__ float memLs[NBANDS], memRs[NBANDS];
    __shared__ float2 lnp[16];
    __shared__ float2 lnf1;

    int tid = threadIdx.x, lane = tid & 31, wid = tid >> 5;
    int b0 = blockIdx.x;                // one batch row per block

    // state init + t=0 mag load
    if (tid < NBANDS) { Qs[tid] = d_q0[tid]; memLs[tid] = 0.f; memRs[tid] = 0.f; }
    for (int i = tid; i < KTOT; i += NTHR) ahr[i] = __float2half_rn(0.f);
    if (tid < 128) hold_s[tid] = 0.f;
    for (int i = tid; i < FFb; i += NTHR)
        magbuf[0][i] = d_mag[(long long)(b0*TT + 0)*FFb + i];
    __syncthreads();

    for (int t = 0; t < TT; t++) {
        const float2* magc = magbuf[t & 1];

        // ---- gammatone filterbank: warp per band, Gaussian recurrence ----
        for (int n = wid; n < NBANDS; n += 16) {
            float Q  = Qs[n];
            float fc = d_fc[n];
            float bw = fc / (Q + 1e-8f) + 1e-8f;
            float inv = 1.0f / bw;
            float rad = 5.0f * bw;
            int kmin = (int)ceilf((fc - rad) * 0.064f);  if (kmin < 0)   kmin = 0;
            int kmax = (int)floorf((fc + rad) * 0.064f); if (kmax > 512) kmax = 512;
            float Dlt = 500.f * inv;
            float c1 = __expf(-0.5f * Dlt * Dlt);
            float c2 = c1 * c1;
            int k = kmin + lane;
            float d0 = ((float)k * 15.625f - fc) * inv;
            float w  = __expf(-0.5f * d0 * d0);
            float u  = __expf(-d0 * Dlt);
            float sw = 0.f, sl = 0.f, sr = 0.f;
            for (; k <= kmax; k += 32) {
                float2 m = magc[k];
                sw += w; sl = fmaf(w, m.x, sl); sr = fmaf(w, m.y, sr);
                w = (w * c1) * u;
                u *= c2;
            }
#pragma unroll
            for (int off = 16; off; off >>= 1) {
                sw += __shfl_down_sync(0xffffffffu, sw, off);
                sl += __shfl_down_sync(0xffffffffu, sl, off);
                sr += __shfl_down_sync(0xffffffffu, sr, off);
            }
            if (lane == 0) {
                float den = 1.0f / (sw + 1e-8f);
                float yl = sl * den, yr = sr * den;
                long long oi = ((long long)b0*TT + t)*NBANDS + n;
                outYL[oi] = yl; outYR[oi] = yr; outQ[oi] = Q;
                float cL = log1pf(fmaxf(yl, 0.f));
                float cR = log1pf(fmaxf(yr, 0.f));
                float mLo = memLs[n], mRo = memRs[n];
                ahr[n]       = __float2half_rn(cL);
                ahr[100 + n] = __float2half_rn(mLo);
                ahr[200 + n] = __float2half_rn(cR);
                ahr[300 + n] = __float2half_rn(mRo);
                memLs[n] = 0.8f * mLo + 0.2f * cL;
                memRs[n] = 0.8f * mRo + 0.2f * cR;
            }
        }
        __syncthreads();

        // ---- GRU GEMM via mma.sync: warp owns 2 col-groups (32 gate cols) ----
        {
            float a00[4] = {0,0,0,0}, a01[4] = {0,0,0,0};   // colgroup 2*wid
            float a10[4] = {0,0,0,0}, a11[4] = {0,0,0,0};   // colgroup 2*wid+1
            const uint4* wp0 = ((const uint4*)d_Wb) + ((2*wid)*NKT)*32 + lane;
            const uint4* wp1 = wp0 + (size_t)NKT*32;
            int q = lane & 3;
            bool alive = (lane < 4);
#pragma unroll 3
            for (int kt = 0; kt < NKT; kt++) {
                uint4 wa = wp0[(size_t)kt * 32];
                uint4 wb = wp1[(size_t)kt * 32];
                unsigned x0 = 0, x2 = 0;
                if (alive) {
                    int kk = kt*16 + 2*q;
                    x0 = *(const unsigned*)&ahr[kk];
                    x2 = *(const unsigned*)&ahr[kk + 8];
                }
                mma16816(a00[0], a00[1], a00[2], a00[3], x0, 0u, x2, 0u, wa.x, wa.y);
                mma16816(a01[0], a01[1], a01[2], a01[3], x0, 0u, x2, 0u, wa.z, wa.w);
                mma16816(a10[0], a10[1], a10[2], a10[3], x0, 0u, x2, 0u, wb.x, wb.y);
                mma16816(a11[0], a11[1], a11[2], a11[3], x0, 0u, x2, 0u, wb.z, wb.w);
            }
            if (alive) {
                int cb = 2*wid*16 + 2*q;
                *(float2*)&gs[cb]      = make_float2(a00[0], a00[1]);
                *(float2*)&gs[cb + 8]  = make_float2(a01[0], a01[1]);
                *(float2*)&gs[cb + 16] = make_float2(a10[0], a10[1]);
                *(float2*)&gs[cb + 24] = make_float2(a11[0], a11[1]);
            }
        }
        __syncthreads();

        // ---- gating (128 threads) + next-step mag prefetch (other 384, looped) ----
        if (tid < 128) {
            int d = tid;
            float gr  = gs[d]       + d_biasc[d];
            float gz  = gs[128 + d] + d_biasc[128 + d];
            float gin = gs[256 + d] + d_biasc[256 + d];
            float ghn = gs[384 + d] + d_biasc[384 + d];
            float rg = 1.f / (1.f + __expf(-gr));
            float zg = 1.f / (1.f + __expf(-gz));
            float ng = tanhf(gin + rg * ghn);
            float hn = (1.f - zg) * ng + zg * hold_s[d];
            hold_s[d] = hn;
            ahr[400 + d] = __float2half_rn(hn);
        } else {
            int tn = (t + 1 < TT) ? t + 1 : t;
            for (int i = tid - 128; i < FFb; i += NTHR - 128)
                magbuf[(t + 1) & 1][i] = d_mag[(long long)(b0*TT + tn)*FFb + i];
        }
        __syncthreads();

        // ---- MLP layer 1 via mma: 16 warps, 8 outputs each ----
        float v1a = 0.f, v1b = 0.f;
        {
            float2 v = mlp_mma8(d_Wm1 + wid*8*32, &ahr[400], lane);
            int c = wid*8 + 2*(lane & 3);
            v1a = v.x + b1[c]; v1b = v.y + b1[c + 1];
            float s1 = v1a + v1b, s2 = v1a*v1a + v1b*v1b;
            s1 += __shfl_xor_sync(0xffffffffu, s1, 1); s1 += __shfl_xor_sync(0xffffffffu, s1, 2);
            s2 += __shfl_xor_sync(0xffffffffu, s2, 1); s2 += __shfl_xor_sync(0xffffffffu, s2, 2);
            if (lane == 0) lnp[wid] = make_float2(s1, s2);
        }
        __syncthreads();
        if (wid == 0) {
            float s1 = 0.f, s2 = 0.f;
            if (lane < 16) { float2 p = lnp[lane]; s1 = p.x; s2 = p.y; }
#pragma unroll
            for (int off = 8; off; off >>= 1) {
                s1 += __shfl_down_sync(0xffffffffu, s1, off);
                s2 += __shfl_down_sync(0xffffffffu, s2, off);
            }
            if (lane == 0) {
                float mean = s1 * (1.f/128.f);
                float var  = s2 * (1.f/128.f) - mean * mean;
                lnf1 = make_float2(mean, rsqrtf(var + 1e-5f));
            }
        }
        __syncthreads();
        if (lane < 4) {
            int c = wid*8 + 2*(lane & 3);
            float2 f = lnf1;
            float x0 = (v1a - f.x) * f.y * g1[c]     + be1[c];
            float x1 = (v1b - f.x) * f.y * g1[c + 1] + be1[c + 1];
            am1[c]     = __float2half_rn(x0 / (1.f + __expf(-x0)));
            am1[c + 1] = __float2half_rn(x1 / (1.f + __expf(-x1)));
        }
        __syncthreads();

        // ---- MLP layer 2 via mma ----
        float v2a = 0.f, v2b = 0.f;
        {
            float2 v = mlp_mma8(d_Wm2 + wid*8*32, &am1[0], lane);
            int c = wid*8 + 2*(lane & 3);
            v2a = v.x + b2[c]; v2b = v.y + b2[c + 1];
            float s1 = v2a + v2b, s2 = v2a*v2a + v2b*v2b;
            s1 += __shfl_xor_sync(0xffffffffu, s1, 1); s1 += __shfl_xor_sync(0xffffffffu, s1, 2);
            s2 += __shfl_xor_sync(0xffffffffu, s2, 1); s2 += __shfl_xor_sync(0xffffffffu, s2, 2);
            if (lane == 0) lnp[wid] = make_float2(s1, s2);
        }
        __syncthreads();
        if (wid == 0) {
            float s1 = 0.f, s2 = 0.f;
            if (lane < 16) { float2 p = lnp[lane]; s1 = p.x; s2 = p.y; }
#pragma unroll
            for (int off = 8; off; off >>= 1) {
                s1 += __shfl_down_sync(0xffffffffu, s1, off);
                s2 += __shfl_down_sync(0xffffffffu, s2, off);
            }
            if (lane == 0) {
                float mean = s1 * (1.f/128.f);
                float var  = s2 * (1.f/128.f) - mean * mean;
                lnf1 = make_float2(mean, rsqrtf(var + 1e-5f));
            }
        }
        __syncthreads();
        if (lane < 4) {
            int c = wid*8 + 2*(lane & 3);
            float2 f = lnf1;
            float x0 = (v2a - f.x) * f.y * g2[c]     + be2[c];
            float x1 = (v2b - f.x) * f.y * g2[c + 1] + be2[c + 1];
            am2[c]     = __float2half_rn(x0 / (1.f + __expf(-x0)));
            am2[c + 1] = __float2half_rn(x1 / (1.f + __expf(-x1)));
        }
        __syncthreads();

        // ---- head + Q update via mma: 13 warps, 8 outputs each ----
        if (wid < 13) {
            float2 v = mlp_mma8(d_Wm3 + wid*8*32, &am2[0], lane);
            if (lane < 4) {
                int c = wid*8 + 2*(lane & 3);
                if (c < NBANDS) {
                    float delta = tanhf(v.x + b3[c]);
                    float qt = d_q0[c] + delta * d_dq[c];
                    float qn = 0.8f * Qs[c] + 0.2f * qt;
                    Qs[c] = fminf(fmaxf(qn, 0.05f), 30.f);
                }
                if (c + 1 < NBANDS) {
                    float delta = tanhf(v.y + b3[c + 1]);
                    float qt = d_q0[c + 1] + delta * d_dq[c + 1];
                    float qn = 0.8f * Qs[c + 1] + 0.2f * qt;
                    Qs[c + 1] = fminf(fmaxf(qn, 0.05f), 30.f);
                }
            }
        }
        __syncthreads();
    }
}

// ---------------- launch ----------------
extern "C" void kernel_launch(void* const* d_in, const int* in_sizes, int n_in,
                              void* d_out, int out_size) {
    const float* wavL = (const float*)d_in[0];
    const float* wavR = (const float*)d_in[1];
    const float* w_ih = (const float*)d_in[2];
    const float* w_hh = (const float*)d_in[3];
    const float* b_ih = (const float*)d_in[4];
    const float* b_hh = (const float*)d_in[5];
    const float* w1  = (const float*)d_in[6];
    const float* b1  = (const float*)d_in[7];
    const float* g1  = (const float*)d_in[8];
    const float* be1 = (const float*)d_in[9];
    const float* w2  = (const float*)d_in[10];
    const float* b2  = (const float*)d_in[11];
    const float* g2  = (const float*)d_in[12];
    const float* be2 = (const float*)d_in[13];
    const float* w3  = (const float*)d_in[14];
    const float* b3  = (const float*)d_in[15];

    long long out_elems = (long long)out_size;
    const long long NYQ = 3LL * BB * TT * NBANDS;       // 1,459,200
    const long long XSZ = (long long)BB * TT * FFb;     // 2,495,232 per X (real plane)
    int realmode = (out_elems < NYQ + 3 * XSZ) ? 1 : 0;

    float* out = (float*)d_out;
    float* outYL = out;
    float* outYR = outYL + (long long)BB * TT * NBANDS;
    float* outQ  = outYR + (long long)BB * TT * NBANDS;
    long long xl_off = NYQ;
    long long xr_off = realmode ? (NYQ + XSZ) : (NYQ + 2 * XSZ);
    float* outXL = out + xl_off;
    float* outXR = out + xr_off;

    const int PREP_N = WB_UINTS + GC + M1_U2 + M2_U2 + M3_U2;
    k_consts<<<1, 128>>>();
    k_prep<<<(PREP_N + 255) / 256, 256>>>(w_ih, w_hh, b_ih, b_hh, w1, w2, w3);
    k_fft<<<BB * TT, 256>>>(wavL, wavR, outXL, outXR, realmode, xl_off, xr_off, out_elems);
    k_steps<<<BB, NTHR>>>(outYL, outYR, outQ,
                          b1, g1, be1, b2, g2, be2, b3);
}